// round 1
// baseline (speedup 1.0000x reference)
#include <cuda_runtime.h>
#include <cstdint>
#include <cstddef>

#define BB 64
#define TT 512
#define EE 300
#define UU 1024
#define G3 3072

// Scratch (static device allocations are the sanctioned workaround; no runtime allocs).
__device__ float g_xp[(size_t)3 * TT * BB * UU];        // [gate][t][b][u]  (~402 MB)
__device__ float g_Rpack[(size_t)128 * 24 * UU];        // [cta][j=gate*8+uu][k] (12.6 MB)

// ---------------------------------------------------------------------------
// Pack recurrent kernel: R[k][gate*U + c*8 + uu]  ->  g_Rpack[((c*24)+gate*8+uu)*U + k]
// ---------------------------------------------------------------------------
__global__ void pack_R_kernel(const float* __restrict__ Rk) {
    int idx = blockIdx.x * blockDim.x + threadIdx.x;
    if (idx >= UU * G3) return;
    int k = idx / G3;
    int n = idx - k * G3;
    int gate = n >> 10;
    int u = n & 1023;
    int c = u >> 3;
    int uu = u & 7;
    g_Rpack[((size_t)(c * 24 + gate * 8 + uu)) * UU + k] = Rk[idx];
}

// ---------------------------------------------------------------------------
// Input GEMM: xp[b,t,n] = sum_e emb[x[b,t]][e] * W[e][n] + bias0[n]
// Tiles 64x64, BK=32 (K padded 300->320), 4x4 per thread, fp32.
// Output scattered to g_xp[gate][t][b][u] (time-major for the scan).
// ---------------------------------------------------------------------------
__global__ void input_gemm_kernel(const int* __restrict__ x,
                                  const float* __restrict__ emb,
                                  const float* __restrict__ W,
                                  const float* __restrict__ bias0) {
    __shared__ float As[32][68];   // [kk][row]
    __shared__ float Bs[32][68];   // [kk][col]
    __shared__ int   toks[64];

    int tid = threadIdx.x;               // 256 threads
    int m0 = blockIdx.y * 64;            // row tile (b*T + t linear)
    int n0 = blockIdx.x * 64;            // col tile
    int g  = n0 >> 10;                   // gate, constant per tile (64 | 1024)

    if (tid < 64) toks[tid] = x[m0 + tid];
    __syncthreads();

    int arow = tid & 63;                 // A-load row
    int aseg = tid >> 6;                 // 0..3 -> 8 consecutive k each
    const float* erow = emb + (size_t)toks[arow] * EE;

    int ty = tid >> 4, tx = tid & 15;
    int r0 = ty * 4, c0 = tx * 4;

    float acc[4][4];
#pragma unroll
    for (int i = 0; i < 4; i++)
#pragma unroll
        for (int j = 0; j < 4; j++) acc[i][j] = 0.f;

    for (int k0 = 0; k0 < 320; k0 += 32) {
        // Load A tile (gathered embedding rows), transposed into [kk][row]
#pragma unroll
        for (int i = 0; i < 8; i++) {
            int kk = aseg * 8 + i;
            int k  = k0 + kk;
            As[kk][arow] = (k < EE) ? erow[k] : 0.f;
        }
        // Load B tile (kernel rows), float4 coalesced
#pragma unroll
        for (int q = 0; q < 2; q++) {
            int f4 = tid * 2 + q;                // 0..511
            int kk = f4 >> 4;
            int c4 = (f4 & 15) * 4;
            int k  = k0 + kk;
            float4 v = make_float4(0.f, 0.f, 0.f, 0.f);
            if (k < EE) v = *(const float4*)(W + (size_t)k * G3 + n0 + c4);
            *(float4*)&Bs[kk][c4] = v;
        }
        __syncthreads();
#pragma unroll
        for (int kk = 0; kk < 32; kk++) {
            float4 a = *(const float4*)&As[kk][r0];
            float4 b = *(const float4*)&Bs[kk][c0];
            acc[0][0] += a.x * b.x; acc[0][1] += a.x * b.y; acc[0][2] += a.x * b.z; acc[0][3] += a.x * b.w;
            acc[1][0] += a.y * b.x; acc[1][1] += a.y * b.y; acc[1][2] += a.y * b.z; acc[1][3] += a.y * b.w;
            acc[2][0] += a.z * b.x; acc[2][1] += a.z * b.y; acc[2][2] += a.z * b.z; acc[2][3] += a.z * b.w;
            acc[3][0] += a.w * b.x; acc[3][1] += a.w * b.y; acc[3][2] += a.w * b.z; acc[3][3] += a.w * b.w;
        }
        __syncthreads();
    }

    float4 bv = *(const float4*)(bias0 + n0 + c0);
    int ubase = (n0 + c0) & 1023;
#pragma unroll
    for (int ii = 0; ii < 4; ii++) {
        int i  = m0 + r0 + ii;
        int bb = i >> 9;       // batch
        int tt = i & 511;      // time
        float4 o;
        o.x = acc[ii][0] + bv.x;
        o.y = acc[ii][1] + bv.y;
        o.z = acc[ii][2] + bv.z;
        o.w = acc[ii][3] + bv.w;
        *(float4*)&g_xp[(((size_t)g * TT + tt) * BB + bb) * UU + ubase] = o;
    }
}

// ---------------------------------------------------------------------------
// One GRU step. 128 CTAs (u-tile of 8) x 256 threads.
// Thread (tx=u lane 0..7, ty=0..31 -> rows 2ty, 2ty+1), 6 accumulators
// (2 rows x 3 gates). K chunked 128 through smem; float4 inner loads.
// h chains through `out`: h_{t-1} = out[b, t-1, :], h_t written to out[b, t, :].
// ---------------------------------------------------------------------------
__global__ void gru_step_kernel(const float* __restrict__ hidden0,
                                const float* __restrict__ bias,
                                float* __restrict__ out,
                                int t, int write_state) {
    __shared__ float hs[64][132];    // [row][kk], pad for banks + f4 align
    __shared__ float Rs[24][132];    // [j][kk]

    int cta = blockIdx.x;            // u0 = cta*8
    int tid = threadIdx.x;
    int tx = tid & 7;
    int ty = tid >> 3;
    int r0 = 2 * ty;

    float az0 = 0.f, ar0 = 0.f, ah0 = 0.f;
    float az1 = 0.f, ar1 = 0.f, ah1 = 0.f;

    // load indices for h chunk: 4 threads per row
    int lrow  = tid >> 2;            // 0..63
    int lane4 = tid & 3;
    const float* hrow = (t == 0) ? (hidden0 + (size_t)lrow * UU)
                                 : (out + ((size_t)lrow * TT + (t - 1)) * UU);

    const float* rbase = g_Rpack + (size_t)cta * 24 * UU;

    for (int k0 = 0; k0 < UU; k0 += 128) {
        // load h chunk [64][128]
#pragma unroll
        for (int i = 0; i < 8; i++) {
            int kk = lane4 * 4 + i * 16;
            float4 v = *(const float4*)(hrow + k0 + kk);
            *(float4*)&hs[lrow][kk] = v;
        }
        // load R chunk [24][128]
#pragma unroll
        for (int q = 0; q < 3; q++) {
            int f4 = q * 256 + tid;          // 0..767
            int j   = f4 >> 5;               // 0..23
            int kk4 = (f4 & 31) * 4;
            float4 v = *(const float4*)(rbase + (size_t)j * UU + k0 + kk4);
            *(float4*)&Rs[j][kk4] = v;
        }
        __syncthreads();

#pragma unroll 4
        for (int kk = 0; kk < 128; kk += 4) {
            float4 h0 = *(const float4*)&hs[r0][kk];
            float4 h1 = *(const float4*)&hs[r0 + 1][kk];
            float4 vz = *(const float4*)&Rs[tx][kk];
            float4 vr = *(const float4*)&Rs[8 + tx][kk];
            float4 vh = *(const float4*)&Rs[16 + tx][kk];
            az0 += h0.x * vz.x + h0.y * vz.y + h0.z * vz.z + h0.w * vz.w;
            ar0 += h0.x * vr.x + h0.y * vr.y + h0.z * vr.z + h0.w * vr.w;
            ah0 += h0.x * vh.x + h0.y * vh.y + h0.z * vh.z + h0.w * vh.w;
            az1 += h1.x * vz.x + h1.y * vz.y + h1.z * vz.z + h1.w * vz.w;
            ar1 += h1.x * vr.x + h1.y * vr.y + h1.z * vr.z + h1.w * vr.w;
            ah1 += h1.x * vh.x + h1.y * vh.y + h1.z * vh.z + h1.w * vh.w;
        }
        __syncthreads();
    }

    int u = cta * 8 + tx;
    const float* rb = bias + G3;     // bias[1]
    float bz = rb[u], br = rb[UU + u], bh = rb[2 * UU + u];

#pragma unroll
    for (int p = 0; p < 2; p++) {
        int b = r0 + p;
        float rz = (p ? az1 : az0) + bz;
        float rr = (p ? ar1 : ar0) + br;
        float rh = (p ? ah1 : ah0) + bh;
        float xz = g_xp[(((size_t)0 * TT + t) * BB + b) * UU + u];
        float xr = g_xp[(((size_t)1 * TT + t) * BB + b) * UU + u];
        float xh = g_xp[(((size_t)2 * TT + t) * BB + b) * UU + u];
        float z  = 1.f / (1.f + expf(-(xz + rz)));
        float rg = 1.f / (1.f + expf(-(xr + rr)));
        float hh = tanhf(xh + rg * rh);
        float hp = (t == 0) ? hidden0[(size_t)b * UU + u]
                            : out[((size_t)b * TT + (t - 1)) * UU + u];
        float hn = z * hp + (1.f - z) * hh;
        out[((size_t)b * TT + t) * UU + u] = hn;
        if (write_state && t == TT - 1)
            out[(size_t)BB * TT * UU + (size_t)b * UU + u] = hn;
    }
}

// ---------------------------------------------------------------------------
// Launch: pack -> input GEMM -> 512 sequential step kernels (graph-capturable).
// ---------------------------------------------------------------------------
extern "C" void kernel_launch(void* const* d_in, const int* in_sizes, int n_in,
                              void* d_out, int out_size) {
    const int*   x      = (const int*)d_in[0];
    const float* hidden = (const float*)d_in[1];
    const float* emb    = (const float*)d_in[2];
    const float* W      = (const float*)d_in[3];
    const float* Rk     = (const float*)d_in[4];
    const float* bias   = (const float*)d_in[5];
    float* out = (float*)d_out;

    int write_state = (out_size >= BB * TT * UU + BB * UU) ? 1 : 0;

    pack_R_kernel<<<(UU * G3 + 255) / 256, 256>>>(Rk);

    dim3 gA(G3 / 64, (BB * TT) / 64);   // (48, 512)
    input_gemm_kernel<<<gA, 256>>>(x, emb, W, bias);

    for (int t = 0; t < TT; t++) {
        gru_step_kernel<<<128, 256>>>(hidden, bias, out, t, write_state);
    }
}

// round 2
// speedup vs baseline: 1.2402x; 1.2402x over previous
#include <cuda_runtime.h>
#include <cstdint>
#include <cstddef>

#define BB 64
#define TT 512
#define EE 300
#define UU 1024
#define G3 3072
#define NCTA 128
#define CHUNK 128
#define NCHUNK (UU / CHUNK)
#define HS_LD 132          // 128 + 4 pad (float4 conflict-free)

// Static device scratch (no runtime allocation allowed).
__device__ float g_xp[(size_t)3 * TT * BB * UU];        // [gate][t][b][u]
__device__ float g_Rpack[(size_t)NCTA * 24 * UU];       // [cta][j=gate*8+uu][k]
__device__ unsigned g_bar;

__global__ void init_bar_kernel() { g_bar = 0u; }

// ---------------------------------------------------------------------------
// Pack recurrent kernel: R[k][gate*U + c*8 + uu] -> g_Rpack[((c*24)+gate*8+uu)*U + k]
// ---------------------------------------------------------------------------
__global__ void pack_R_kernel(const float* __restrict__ Rk) {
    int idx = blockIdx.x * blockDim.x + threadIdx.x;
    if (idx >= UU * G3) return;
    int k = idx / G3;
    int n = idx - k * G3;
    int gate = n >> 10;
    int u = n & 1023;
    int c = u >> 3;
    int uu = u & 7;
    g_Rpack[((size_t)(c * 24 + gate * 8 + uu)) * UU + k] = Rk[idx];
}

// ---------------------------------------------------------------------------
// Input GEMM: xp[b,t,n] = sum_e emb[x[b,t]][e] * W[e][n] + bias0[n]
// 64x64 tiles, BK=32, 4x4 per thread, fp32. Writes g_xp[gate][t][b][u].
// ---------------------------------------------------------------------------
__global__ void input_gemm_kernel(const int* __restrict__ x,
                                  const float* __restrict__ emb,
                                  const float* __restrict__ W,
                                  const float* __restrict__ bias0) {
    __shared__ float As[32][68];
    __shared__ float Bs[32][68];
    __shared__ int   toks[64];

    int tid = threadIdx.x;
    int m0 = blockIdx.y * 64;
    int n0 = blockIdx.x * 64;
    int g  = n0 >> 10;

    if (tid < 64) toks[tid] = x[m0 + tid];
    __syncthreads();

    int arow = tid & 63;
    int aseg = tid >> 6;
    const float* erow = emb + (size_t)toks[arow] * EE;

    int ty = tid >> 4, tx = tid & 15;
    int r0 = ty * 4, c0 = tx * 4;

    float acc[4][4];
#pragma unroll
    for (int i = 0; i < 4; i++)
#pragma unroll
        for (int j = 0; j < 4; j++) acc[i][j] = 0.f;

    for (int k0 = 0; k0 < 320; k0 += 32) {
#pragma unroll
        for (int i = 0; i < 8; i++) {
            int kk = aseg * 8 + i;
            int k  = k0 + kk;
            As[kk][arow] = (k < EE) ? erow[k] : 0.f;
        }
#pragma unroll
        for (int q = 0; q < 2; q++) {
            int f4 = tid * 2 + q;
            int kk = f4 >> 4;
            int c4 = (f4 & 15) * 4;
            int k  = k0 + kk;
            float4 v = make_float4(0.f, 0.f, 0.f, 0.f);
            if (k < EE) v = *(const float4*)(W + (size_t)k * G3 + n0 + c4);
            *(float4*)&Bs[kk][c4] = v;
        }
        __syncthreads();
#pragma unroll
        for (int kk = 0; kk < 32; kk++) {
            float4 a = *(const float4*)&As[kk][r0];
            float4 b = *(const float4*)&Bs[kk][c0];
            acc[0][0] += a.x * b.x; acc[0][1] += a.x * b.y; acc[0][2] += a.x * b.z; acc[0][3] += a.x * b.w;
            acc[1][0] += a.y * b.x; acc[1][1] += a.y * b.y; acc[1][2] += a.y * b.z; acc[1][3] += a.y * b.w;
            acc[2][0] += a.z * b.x; acc[2][1] += a.z * b.y; acc[2][2] += a.z * b.z; acc[2][3] += a.z * b.w;
            acc[3][0] += a.w * b.x; acc[3][1] += a.w * b.y; acc[3][2] += a.w * b.z; acc[3][3] += a.w * b.w;
        }
        __syncthreads();
    }

    float4 bv = *(const float4*)(bias0 + n0 + c0);
    int ubase = (n0 + c0) & 1023;
#pragma unroll
    for (int ii = 0; ii < 4; ii++) {
        int i  = m0 + r0 + ii;
        int bb = i >> 9;
        int tt = i & 511;
        float4 o;
        o.x = acc[ii][0] + bv.x;
        o.y = acc[ii][1] + bv.y;
        o.z = acc[ii][2] + bv.z;
        o.w = acc[ii][3] + bv.w;
        *(float4*)&g_xp[(((size_t)g * TT + tt) * BB + bb) * UU + ubase] = o;
    }
}

// ---------------------------------------------------------------------------
// Persistent GRU scan. 128 CTAs x 256 threads, all co-resident (1 CTA/SM).
// Each CTA owns 8 u-values x 3 gates; R slice lives in smem for all 512 steps.
// h chunks double-buffered via cp.async. Grid barrier between steps.
// ---------------------------------------------------------------------------
__device__ __forceinline__ void cpa16(float* dst, const float* src) {
    unsigned d = (unsigned)__cvta_generic_to_shared(dst);
    asm volatile("cp.async.cg.shared.global [%0], [%1], 16;\n" :: "r"(d), "l"(src));
}
__device__ __forceinline__ void cpa_commit() {
    asm volatile("cp.async.commit_group;\n");
}

__device__ __forceinline__ void load_chunk(float* buf, const float* hbase,
                                           size_t rstride, int k0, int tid) {
    int r  = tid >> 2;                 // 0..63 (4 threads per row)
    int q4 = (tid & 3) * 4;            // float offset base within row
    const float* srow = hbase + (size_t)r * rstride + k0;
    float* drow = buf + r * HS_LD;
#pragma unroll
    for (int it = 0; it < 8; it++) {
        int kf = q4 + it * 16;
        cpa16(drow + kf, srow + kf);
    }
}

__global__ void __launch_bounds__(256, 1)
gru_persistent_kernel(const float* __restrict__ hidden0,
                      const float* __restrict__ bias,
                      float* __restrict__ out,
                      int write_state) {
    extern __shared__ float smem[];
    float* Rs  = smem;                        // [24][1024]   96 KB
    float* hsm = Rs + 24 * UU;                // [2][64][132] 66 KB
    float* stg = hsm + 2 * 64 * HS_LD;        // [3][64][9]    7 KB

    int tid  = threadIdx.x;
    int cta  = blockIdx.x;
    int lane = tid & 31;                      // compute rows: lane, lane+32
    int w    = tid >> 5;                      // compute u-index 0..7

    // Load R slice once (coalesced).
    {
        const float4* rsrc = (const float4*)(g_Rpack + (size_t)cta * 24 * UU);
        float4* rdst = (float4*)Rs;
        for (int i = tid; i < 24 * UU / 4; i += 256) rdst[i] = rsrc[i];
    }

    // Epilogue mapping: lanes sweep u (coalesced global access).
    int eu  = lane & 7;
    int ebq = lane >> 3;
    int eb0 = w * 4 + ebq;                    // rows eb0, eb0+32
    int u0  = cta * 8;
    int u   = u0 + eu;
    float bz = bias[G3 + u];
    float br = bias[G3 + UU + u];
    float bh = bias[G3 + 2 * UU + u];

    __syncthreads();

    unsigned target = 0;
    for (int t = 0; t < TT; t++) {
        const float* hbase;
        size_t rstride;
        if (t == 0) { hbase = hidden0;                      rstride = UU; }
        else        { hbase = out + (size_t)(t - 1) * UU;   rstride = (size_t)TT * UU; }

        // Prefetch xp + h_prev (epilogue mapping) — consumed after the GEMM.
        float xz0 = g_xp[(((size_t)0 * TT + t) * BB + eb0)      * UU + u];
        float xr0 = g_xp[(((size_t)1 * TT + t) * BB + eb0)      * UU + u];
        float xh0 = g_xp[(((size_t)2 * TT + t) * BB + eb0)      * UU + u];
        float xz1 = g_xp[(((size_t)0 * TT + t) * BB + eb0 + 32) * UU + u];
        float xr1 = g_xp[(((size_t)1 * TT + t) * BB + eb0 + 32) * UU + u];
        float xh1 = g_xp[(((size_t)2 * TT + t) * BB + eb0 + 32) * UU + u];
        float hp0 = hbase[(size_t)eb0 * rstride + u];
        float hp1 = hbase[(size_t)(eb0 + 32) * rstride + u];

        float az0 = 0.f, ar0 = 0.f, ah0 = 0.f;
        float az1 = 0.f, ar1 = 0.f, ah1 = 0.f;

        load_chunk(hsm, hbase, rstride, 0, tid);
        cpa_commit();

        for (int c = 0; c < NCHUNK; c++) {
            if (c + 1 < NCHUNK) {
                load_chunk(hsm + ((c + 1) & 1) * 64 * HS_LD, hbase, rstride,
                           (c + 1) * CHUNK, tid);
                cpa_commit();
                asm volatile("cp.async.wait_group 1;\n");
            } else {
                asm volatile("cp.async.wait_group 0;\n");
            }
            __syncthreads();

            const float* hb = hsm + (c & 1) * 64 * HS_LD;
            int k0 = c * CHUNK;
            const float* rz = Rs + (size_t)w * UU + k0;
            const float* rr = Rs + (size_t)(8 + w) * UU + k0;
            const float* rh = Rs + (size_t)(16 + w) * UU + k0;
            const float* h0p = hb + lane * HS_LD;
            const float* h1p = hb + (lane + 32) * HS_LD;

#pragma unroll 8
            for (int kk = 0; kk < CHUNK; kk += 4) {
                float4 h0 = *(const float4*)(h0p + kk);
                float4 h1 = *(const float4*)(h1p + kk);
                float4 vz = *(const float4*)(rz + kk);
                float4 vr = *(const float4*)(rr + kk);
                float4 vh = *(const float4*)(rh + kk);
                az0 += h0.x * vz.x + h0.y * vz.y + h0.z * vz.z + h0.w * vz.w;
                ar0 += h0.x * vr.x + h0.y * vr.y + h0.z * vr.z + h0.w * vr.w;
                ah0 += h0.x * vh.x + h0.y * vh.y + h0.z * vh.z + h0.w * vh.w;
                az1 += h1.x * vz.x + h1.y * vz.y + h1.z * vz.z + h1.w * vz.w;
                ar1 += h1.x * vr.x + h1.y * vr.y + h1.z * vr.z + h1.w * vr.w;
                ah1 += h1.x * vh.x + h1.y * vh.y + h1.z * vh.z + h1.w * vh.w;
            }
            __syncthreads();
        }

        // Stage accumulators for transposed (coalesced) epilogue.
        stg[(0 * 64 + lane) * 9 + w] = az0;
        stg[(0 * 64 + lane + 32) * 9 + w] = az1;
        stg[(1 * 64 + lane) * 9 + w] = ar0;
        stg[(1 * 64 + lane + 32) * 9 + w] = ar1;
        stg[(2 * 64 + lane) * 9 + w] = ah0;
        stg[(2 * 64 + lane + 32) * 9 + w] = ah1;
        __syncthreads();

#pragma unroll
        for (int p = 0; p < 2; p++) {
            int b = eb0 + p * 32;
            float az = stg[(0 * 64 + b) * 9 + eu];
            float ar = stg[(1 * 64 + b) * 9 + eu];
            float ah = stg[(2 * 64 + b) * 9 + eu];
            float xz = p ? xz1 : xz0;
            float xr = p ? xr1 : xr0;
            float xh = p ? xh1 : xh0;
            float hp = p ? hp1 : hp0;
            float z  = 1.f / (1.f + expf(-(xz + az + bz)));
            float rg = 1.f / (1.f + expf(-(xr + ar + br)));
            float hh = tanhf(xh + rg * (ah + bh));
            float hn = z * hp + (1.f - z) * hh;
            out[(size_t)b * TT * UU + (size_t)t * UU + u] = hn;
            if (write_state && t == TT - 1)
                out[(size_t)BB * TT * UU + (size_t)b * UU + u] = hn;
        }

        // Grid barrier (all 128 CTAs co-resident).
        target += NCTA;
        __syncthreads();
        if (tid == 0) {
            __threadfence();
            atomicAdd(&g_bar, 1u);
            while (*(volatile unsigned*)&g_bar < target) { }
        }
        __syncthreads();
    }
}

// ---------------------------------------------------------------------------
extern "C" void kernel_launch(void* const* d_in, const int* in_sizes, int n_in,
                              void* d_out, int out_size) {
    const int*   x      = (const int*)d_in[0];
    const float* hidden = (const float*)d_in[1];
    const float* emb    = (const float*)d_in[2];
    const float* W      = (const float*)d_in[3];
    const float* Rk     = (const float*)d_in[4];
    const float* bias   = (const float*)d_in[5];
    float* out = (float*)d_out;

    int write_state = (out_size >= BB * TT * UU + BB * UU) ? 1 : 0;

    static int attr_done = 0;
    if (!attr_done) {
        cudaFuncSetAttribute(gru_persistent_kernel,
                             cudaFuncAttributeMaxDynamicSharedMemorySize,
                             (24 * UU + 2 * 64 * HS_LD + 3 * 64 * 9) * 4);
        attr_done = 1;
    }

    init_bar_kernel<<<1, 1>>>();
    pack_R_kernel<<<(UU * G3 + 255) / 256, 256>>>(Rk);

    dim3 gA(G3 / 64, (BB * TT) / 64);
    input_gemm_kernel<<<gA, 256>>>(x, emb, W, bias);

    size_t shbytes = (size_t)(24 * UU + 2 * 64 * HS_LD + 3 * 64 * 9) * 4;
    gru_persistent_kernel<<<NCTA, 256, shbytes>>>(hidden, bias, out, write_state);
}

// round 5
// speedup vs baseline: 2.0803x; 1.6774x over previous
#include <cuda_runtime.h>
#include <cuda_bf16.h>
#include <mma.h>
#include <cstdint>
#include <cstddef>

using namespace nvcuda;

#define BB 64
#define TT 512
#define EE 300
#define UU 1024
#define G3 3072
#define NCTA 144           // 24 m-tiles x 6 k-slices
#define NSL 6
#define KSL 512
#define A_PITCH 520        // 512 + 8 pad (conflict-free ldmatrix)
#define A_BYTES (128 * A_PITCH * 2)       // 133120
#define B_PITCH 136        // 128 + 8 pad
#define BCH_BYTES (64 * B_PITCH * 2)      // 17408
#define SMEM_BYTES (A_BYTES + 4 * BCH_BYTES)

// ---- static device scratch ----
__device__ float g_xp[(size_t)3 * TT * BB * UU];                     // [gate][t][b][u]
__device__ __align__(16) __nv_bfloat16 g_Apack[(size_t)NCTA * 128 * A_PITCH];
__device__ __align__(16) __nv_bfloat16 g_Bhi[BB * UU];
__device__ __align__(16) __nv_bfloat16 g_Blo[BB * UU];
__device__ float g_Pp[(size_t)NSL * BB * G3];                        // [slice][b][m]
__device__ unsigned g_bar;

__global__ void init_bar_kernel() { g_bar = 0u; }

__device__ __forceinline__ void cp16(void* dst, const void* src) {
    unsigned d = (unsigned)__cvta_generic_to_shared(dst);
    asm volatile("cp.async.cg.shared.global [%0], [%1], 16;\n" :: "r"(d), "l"(src));
}
__device__ __forceinline__ void cpa_commit() {
    asm volatile("cp.async.commit_group;\n");
}
__device__ __forceinline__ unsigned packbf2(float a, float b) {
    __nv_bfloat16 ha = __float2bfloat16(a), hb = __float2bfloat16(b);
    unsigned short ua = *(unsigned short*)&ha, ub = *(unsigned short*)&hb;
    return (unsigned)ua | ((unsigned)ub << 16);
}

// ---------------------------------------------------------------------------
// Pack A' slices. cta = mt*6 + s; slice s: region r = s>>1 (0:Rhi,1:Rhi,2:Rlo),
// k = (s&1)*512 + j. A'[m][j] = R{hi|lo}[k][m], m = mt*128 + m_local.
// ---------------------------------------------------------------------------
__global__ void pack_A_kernel(const float* __restrict__ Rk) {
    size_t idx = (size_t)blockIdx.x * 256 + threadIdx.x;
    if (idx >= (size_t)G3 * G3) return;
    int m  = (int)(idx / G3);
    int kp = (int)(idx - (size_t)m * G3);
    int s = kp >> 9;
    int j = kp & 511;
    int k = ((s & 1) << 9) + j;
    int region = s >> 1;
    float v = Rk[(size_t)k * G3 + m];
    __nv_bfloat16 hi = __float2bfloat16(v);
    __nv_bfloat16 wv = (region == 2) ? __float2bfloat16(v - __bfloat162float(hi)) : hi;
    int mt = m >> 7, ml = m & 127;
    g_Apack[(size_t)(mt * NSL + s) * (128 * A_PITCH) + ml * A_PITCH + j] = wv;
}

// ---------------------------------------------------------------------------
// Initial B' from hidden0.
// ---------------------------------------------------------------------------
__global__ void prep_B_kernel(const float* __restrict__ hidden0) {
    int idx = blockIdx.x * 256 + threadIdx.x;
    if (idx >= BB * UU) return;
    float v = hidden0[idx];
    __nv_bfloat16 hi = __float2bfloat16(v);
    g_Bhi[idx] = hi;
    g_Blo[idx] = __float2bfloat16(v - __bfloat162float(hi));
}

// ---------------------------------------------------------------------------
// Input GEMM (fp32 SIMT): xp -> g_xp[gate][t][b][u]
// ---------------------------------------------------------------------------
__global__ void input_gemm_kernel(const int* __restrict__ x,
                                  const float* __restrict__ emb,
                                  const float* __restrict__ W,
                                  const float* __restrict__ bias0) {
    __shared__ float As[32][68];
    __shared__ float Bs[32][68];
    __shared__ int   toks[64];

    int tid = threadIdx.x;
    int m0 = blockIdx.y * 64;
    int n0 = blockIdx.x * 64;
    int g  = n0 >> 10;

    if (tid < 64) toks[tid] = x[m0 + tid];
    __syncthreads();

    int arow = tid & 63;
    int aseg = tid >> 6;
    const float* erow = emb + (size_t)toks[arow] * EE;

    int ty = tid >> 4, tx = tid & 15;
    int r0 = ty * 4, c0 = tx * 4;

    float acc[4][4];
#pragma unroll
    for (int i = 0; i < 4; i++)
#pragma unroll
        for (int j = 0; j < 4; j++) acc[i][j] = 0.f;

    for (int k0 = 0; k0 < 320; k0 += 32) {
#pragma unroll
        for (int i = 0; i < 8; i++) {
            int kk = aseg * 8 + i;
            int k  = k0 + kk;
            As[kk][arow] = (k < EE) ? erow[k] : 0.f;
        }
#pragma unroll
        for (int q = 0; q < 2; q++) {
            int f4 = tid * 2 + q;
            int kk = f4 >> 4;
            int c4 = (f4 & 15) * 4;
            int k  = k0 + kk;
            float4 v = make_float4(0.f, 0.f, 0.f, 0.f);
            if (k < EE) v = *(const float4*)(W + (size_t)k * G3 + n0 + c4);
            *(float4*)&Bs[kk][c4] = v;
        }
        __syncthreads();
#pragma unroll
        for (int kk = 0; kk < 32; kk++) {
            float4 a = *(const float4*)&As[kk][r0];
            float4 b = *(const float4*)&Bs[kk][c0];
            acc[0][0] += a.x * b.x; acc[0][1] += a.x * b.y; acc[0][2] += a.x * b.z; acc[0][3] += a.x * b.w;
            acc[1][0] += a.y * b.x; acc[1][1] += a.y * b.y; acc[1][2] += a.y * b.z; acc[1][3] += a.y * b.w;
            acc[2][0] += a.z * b.x; acc[2][1] += a.z * b.y; acc[2][2] += a.z * b.z; acc[2][3] += a.z * b.w;
            acc[3][0] += a.w * b.x; acc[3][1] += a.w * b.y; acc[3][2] += a.w * b.z; acc[3][3] += a.w * b.w;
        }
        __syncthreads();
    }

    float4 bv = *(const float4*)(bias0 + n0 + c0);
    int ubase = (n0 + c0) & 1023;
#pragma unroll
    for (int ii = 0; ii < 4; ii++) {
        int i  = m0 + r0 + ii;
        int bb = i >> 9;
        int tt = i & 511;
        float4 o;
        o.x = acc[ii][0] + bv.x;
        o.y = acc[ii][1] + bv.y;
        o.z = acc[ii][2] + bv.z;
        o.w = acc[ii][3] + bv.w;
        *(float4*)&g_xp[(((size_t)g * TT + tt) * BB + bb) * UU + ubase] = o;
    }
}

// ---------------------------------------------------------------------------
// Persistent WMMA GRU scan. 144 CTAs x 256 threads, 1 CTA/SM.
// A slice resident in smem; per step stream B slice (4 chunks), 1024 wmma,
// store partials to g_Pp[s][b][m], barrier, epilogue on CTAs 0..63, barrier.
// ---------------------------------------------------------------------------
__device__ __forceinline__ void gbar_sync(unsigned target) {
    __syncthreads();
    if (threadIdx.x == 0) {
        __threadfence();
        atomicAdd(&g_bar, 1u);
        while (*(volatile unsigned*)&g_bar < target) { }
        __threadfence();
    }
    __syncthreads();
}

__global__ void __launch_bounds__(256, 1)
gru_wmma_kernel(const float* __restrict__ hidden0,
                const float* __restrict__ bias,
                float* __restrict__ out,
                int write_state) {
    extern __shared__ unsigned char sm[];
    __nv_bfloat16* Asm = (__nv_bfloat16*)sm;
    unsigned char* Bsm = sm + A_BYTES;

    int tid = threadIdx.x;
    int cta = blockIdx.x;
    int mt = cta / NSL;
    int s  = cta - mt * NSL;
    int w  = tid >> 5;
    int wm = w & 3;          // m-group (32 rows)
    int wn = w >> 2;         // n-group (32 cols)

    // Load resident A slice once.
    {
        const unsigned char* src = (const unsigned char*)g_Apack + (size_t)cta * A_BYTES;
        for (int i = tid; i < A_BYTES / 16; i += 256)
            cp16(sm + (size_t)i * 16, src + (size_t)i * 16);
        cpa_commit();
        asm volatile("cp.async.wait_group 0;\n");
    }
    __syncthreads();

    const __nv_bfloat16* bsrc = ((s >> 1) == 1) ? g_Blo : g_Bhi;
    int kbase = (s & 1) * KSL;
    int brow = tid >> 2;     // 0..63 (B row per thread)
    int bq   = tid & 3;

    // Epilogue constants (CTA b = cta < 64, u = tid*4).
    int u4 = tid * 4;
    float4 bz4 = make_float4(0, 0, 0, 0), br4 = bz4, bh4 = bz4;
    if (cta < BB) {
        bz4 = *(const float4*)&bias[G3 + u4];
        br4 = *(const float4*)&bias[G3 + UU + u4];
        bh4 = *(const float4*)&bias[G3 + 2 * UU + u4];
    }

    const __nv_bfloat16* Aw = Asm + (size_t)(wm * 32) * A_PITCH;
    float* gp = g_Pp + ((size_t)s * BB) * G3 + (size_t)(wn * 32) * G3 + mt * 128 + wm * 32;

    unsigned tgt = 0;
    for (int t = 0; t < TT; t++) {
        // Issue all 4 B-chunk copies (B for step t is ready: prep kernel or prior epilogue).
#pragma unroll
        for (int kc = 0; kc < 4; kc++) {
            const unsigned char* srow = (const unsigned char*)
                (bsrc + (size_t)brow * UU + kbase + kc * 128) + bq * 64;
            unsigned char* drow = Bsm + kc * BCH_BYTES + brow * (B_PITCH * 2) + bq * 64;
#pragma unroll
            for (int i = 0; i < 4; i++) cp16(drow + i * 16, srow + i * 16);
            cpa_commit();
        }

        wmma::fragment<wmma::accumulator, 16, 16, 16, float> acc[2][2];
#pragma unroll
        for (int i = 0; i < 2; i++)
#pragma unroll
            for (int j = 0; j < 2; j++) wmma::fill_fragment(acc[i][j], 0.0f);

#pragma unroll
        for (int kc = 0; kc < 4; kc++) {
            if      (kc == 0) asm volatile("cp.async.wait_group 3;\n");
            else if (kc == 1) asm volatile("cp.async.wait_group 2;\n");
            else if (kc == 2) asm volatile("cp.async.wait_group 1;\n");
            else              asm volatile("cp.async.wait_group 0;\n");
            __syncthreads();

            const __nv_bfloat16* Bb = (const __nv_bfloat16*)(Bsm + kc * BCH_BYTES);
#pragma unroll
            for (int kk = 0; kk < 8; kk++) {
                int kof = kc * 128 + kk * 16;
                wmma::fragment<wmma::matrix_a, 16, 16, 16, __nv_bfloat16, wmma::row_major> af[2];
                wmma::fragment<wmma::matrix_b, 16, 16, 16, __nv_bfloat16, wmma::col_major> bf[2];
                wmma::load_matrix_sync(af[0], Aw + kof, A_PITCH);
                wmma::load_matrix_sync(af[1], Aw + (size_t)16 * A_PITCH + kof, A_PITCH);
                wmma::load_matrix_sync(bf[0], Bb + (size_t)(wn * 32) * B_PITCH + kk * 16, B_PITCH);
                wmma::load_matrix_sync(bf[1], Bb + (size_t)(wn * 32 + 16) * B_PITCH + kk * 16, B_PITCH);
                wmma::mma_sync(acc[0][0], af[0], bf[0], acc[0][0]);
                wmma::mma_sync(acc[0][1], af[0], bf[1], acc[0][1]);
                wmma::mma_sync(acc[1][0], af[1], bf[0], acc[1][0]);
                wmma::mma_sync(acc[1][1], af[1], bf[1], acc[1][1]);
            }
        }

        // Store partials to g_Pp[s][b][m] (col_major: (m,n)->ptr[m + n*ldm]).
#pragma unroll
        for (int i = 0; i < 2; i++)
#pragma unroll
            for (int j = 0; j < 2; j++)
                wmma::store_matrix_sync(gp + (size_t)j * 16 * G3 + i * 16,
                                        acc[i][j], G3, wmma::mem_col_major);

        tgt += NCTA; gbar_sync(tgt);

        // Epilogue: CTA b = cta (<64), thread covers u4..u4+3.
        if (cta < BB) {
            int b = cta;
            float sz[4] = {0, 0, 0, 0}, sr[4] = {0, 0, 0, 0}, sh[4] = {0, 0, 0, 0};
#pragma unroll
            for (int si = 0; si < NSL; si++) {
                const float* pb = g_Pp + ((size_t)si * BB + b) * G3;
                float4 vz = *(const float4*)(pb + u4);
                float4 vr = *(const float4*)(pb + 1024 + u4);
                float4 vh = *(const float4*)(pb + 2048 + u4);
                sz[0] += vz.x; sz[1] += vz.y; sz[2] += vz.z; sz[3] += vz.w;
                sr[0] += vr.x; sr[1] += vr.y; sr[2] += vr.z; sr[3] += vr.w;
                sh[0] += vh.x; sh[1] += vh.y; sh[2] += vh.z; sh[3] += vh.w;
            }
            float4 xz = *(const float4*)&g_xp[(((size_t)0 * TT + t) * BB + b) * UU + u4];
            float4 xr = *(const float4*)&g_xp[(((size_t)1 * TT + t) * BB + b) * UU + u4];
            float4 xh = *(const float4*)&g_xp[(((size_t)2 * TT + t) * BB + b) * UU + u4];
            float4 hp = (t == 0)
                ? *(const float4*)&hidden0[(size_t)b * UU + u4]
                : *(const float4*)&out[((size_t)b * TT + (t - 1)) * UU + u4];
            float xzv[4] = {xz.x, xz.y, xz.z, xz.w};
            float xrv[4] = {xr.x, xr.y, xr.z, xr.w};
            float xhv[4] = {xh.x, xh.y, xh.z, xh.w};
            float hpv[4] = {hp.x, hp.y, hp.z, hp.w};
            float bzv[4] = {bz4.x, bz4.y, bz4.z, bz4.w};
            float brv[4] = {br4.x, br4.y, br4.z, br4.w};
            float bhv[4] = {bh4.x, bh4.y, bh4.z, bh4.w};
            float hn[4], lo[4];
#pragma unroll
            for (int j = 0; j < 4; j++) {
                float z  = 1.f / (1.f + expf(-(xzv[j] + sz[j] + bzv[j])));
                float rg = 1.f / (1.f + expf(-(xrv[j] + sr[j] + brv[j])));
                float hh = tanhf(xhv[j] + rg * (sh[j] + bhv[j]));
                hn[j] = z * hpv[j] + (1.f - z) * hh;
                __nv_bfloat16 hi = __float2bfloat16(hn[j]);
                lo[j] = hn[j] - __bfloat162float(hi);
            }
            *(float4*)&out[((size_t)b * TT + t) * UU + u4] =
                make_float4(hn[0], hn[1], hn[2], hn[3]);
            *(uint2*)&g_Bhi[(size_t)b * UU + u4] =
                make_uint2(packbf2(hn[0], hn[1]), packbf2(hn[2], hn[3]));
            *(uint2*)&g_Blo[(size_t)b * UU + u4] =
                make_uint2(packbf2(lo[0], lo[1]), packbf2(lo[2], lo[3]));
            if (write_state && t == TT - 1)
                *(float4*)&out[(size_t)BB * TT * UU + (size_t)b * UU + u4] =
                    make_float4(hn[0], hn[1], hn[2], hn[3]);
        }

        tgt += NCTA; gbar_sync(tgt);
    }
}

// ---------------------------------------------------------------------------
extern "C" void kernel_launch(void* const* d_in, const int* in_sizes, int n_in,
                              void* d_out, int out_size) {
    const int*   x      = (const int*)d_in[0];
    const float* hidden = (const float*)d_in[1];
    const float* emb    = (const float*)d_in[2];
    const float* W      = (const float*)d_in[3];
    const float* Rk     = (const float*)d_in[4];
    const float* bias   = (const float*)d_in[5];
    float* out = (float*)d_out;

    int write_state = (out_size >= BB * TT * UU + BB * UU) ? 1 : 0;

    static int attr_done = 0;
    if (!attr_done) {
        cudaFuncSetAttribute(gru_wmma_kernel,
                             cudaFuncAttributeMaxDynamicSharedMemorySize, SMEM_BYTES);
        attr_done = 1;
    }

    init_bar_kernel<<<1, 1>>>();

    size_t ae = (size_t)G3 * G3;
    pack_A_kernel<<<(unsigned)((ae + 255) / 256), 256>>>(Rk);
    prep_B_kernel<<<(BB * UU + 255) / 256, 256>>>(hidden);

    dim3 gA(G3 / 64, (BB * TT) / 64);
    input_gemm_kernel<<<gA, 256>>>(x, emb, W, bias);

    gru_wmma_kernel<<<NCTA, 256, SMEM_BYTES>>>(hidden, bias, out, write_state);
}

// round 6
// speedup vs baseline: 2.1717x; 1.0439x over previous
#include <cuda_runtime.h>
#include <cuda_bf16.h>
#include <mma.h>
#include <cstdint>
#include <cstddef>

using namespace nvcuda;

#define BB 64
#define TT 512
#define EE 300
#define UU 1024
#define G3 3072
#define NCTA 144           // 24 m-tiles x 6 k-slices
#define NSL 6
#define KSL 512
#define A_PITCH 520        // 512 + 8 pad (conflict-free ldmatrix)
#define A_BYTES (128 * A_PITCH * 2)       // 133120
#define B_PITCH 136        // 128 + 8 pad
#define BCH_BYTES (64 * B_PITCH * 2)      // 17408
#define SMEM_BYTES (A_BYTES + 4 * BCH_BYTES)
#define NU (BB * (UU / 4))                // 16384 epilogue units (float4 over u)
#define UPC 114                           // ceil(NU / NCTA)

// ---- static device scratch ----
__device__ float g_xp[(size_t)3 * TT * BB * UU];                     // [gate][t][b][u]
__device__ __align__(16) __nv_bfloat16 g_Apack[(size_t)NCTA * 128 * A_PITCH];
__device__ __align__(16) __nv_bfloat16 g_Bcat[(size_t)BB * G3];      // [b][hhi|hlo|hhi]
__device__ float g_Pp[(size_t)NSL * BB * G3];                        // [slice][b][m]
__device__ unsigned g_bar;

__global__ void init_bar_kernel() { g_bar = 0u; }

__device__ __forceinline__ void cp16(void* dst, const void* src) {
    unsigned d = (unsigned)__cvta_generic_to_shared(dst);
    asm volatile("cp.async.cg.shared.global [%0], [%1], 16;\n" :: "r"(d), "l"(src));
}
__device__ __forceinline__ void cpa_commit() {
    asm volatile("cp.async.commit_group;\n");
}
__device__ __forceinline__ unsigned packbf2(float a, float b) {
    __nv_bfloat16 ha = __float2bfloat16(a), hb = __float2bfloat16(b);
    unsigned short ua = *(unsigned short*)&ha, ub = *(unsigned short*)&hb;
    return (unsigned)ua | ((unsigned)ub << 16);
}

// ---------------------------------------------------------------------------
// Pack A' slices. cta = mt*6 + s; region r = s>>1 (0:Rhi,1:Rhi... actually
// s in {0,1}:Rhi k 0..1023 ; {2,3}:Rlo ; {4,5}:Rhi again — matched to
// B' = [hhi|hlo|hhi]: products hi*hi + lo*hlo? See mapping below:
//   slice s covers k' = s*512..s*512+511 of K'=3072:
//   k'<1024   : Rhi[k'] * hhi[k']
//   1024..2047: Rhi[k'-1024] * hlo[k'-1024]
//   2048..3071: Rlo[k'-2048] * hhi[k'-2048]
// ---------------------------------------------------------------------------
__global__ void pack_A_kernel(const float* __restrict__ Rk) {
    size_t idx = (size_t)blockIdx.x * 256 + threadIdx.x;
    if (idx >= (size_t)G3 * G3) return;
    int m  = (int)(idx / G3);
    int kp = (int)(idx - (size_t)m * G3);
    int s = kp >> 9;
    int j = kp & 511;
    int k = ((s & 1) << 9) + j;
    int region = s >> 1;
    float v = Rk[(size_t)k * G3 + m];
    __nv_bfloat16 hi = __float2bfloat16(v);
    __nv_bfloat16 wv = (region == 2) ? __float2bfloat16(v - __bfloat162float(hi)) : hi;
    int mt = m >> 7, ml = m & 127;
    g_Apack[(size_t)(mt * NSL + s) * (128 * A_PITCH) + ml * A_PITCH + j] = wv;
}

// ---------------------------------------------------------------------------
// Initial B' from hidden0: Bcat[b][u]=hhi, [1024+u]=hlo, [2048+u]=hhi.
// ---------------------------------------------------------------------------
__global__ void prep_B_kernel(const float* __restrict__ hidden0) {
    int idx = blockIdx.x * 256 + threadIdx.x;
    if (idx >= BB * UU) return;
    int b = idx >> 10, u = idx & 1023;
    float v = hidden0[idx];
    __nv_bfloat16 hi = __float2bfloat16(v);
    __nv_bfloat16 lo = __float2bfloat16(v - __bfloat162float(hi));
    g_Bcat[(size_t)b * G3 + u] = hi;
    g_Bcat[(size_t)b * G3 + 1024 + u] = lo;
    g_Bcat[(size_t)b * G3 + 2048 + u] = hi;
}

// ---------------------------------------------------------------------------
// Input GEMM (fp32 SIMT): xp -> g_xp[gate][t][b][u]
// ---------------------------------------------------------------------------
__global__ void input_gemm_kernel(const int* __restrict__ x,
                                  const float* __restrict__ emb,
                                  const float* __restrict__ W,
                                  const float* __restrict__ bias0) {
    __shared__ float As[32][68];
    __shared__ float Bs[32][68];
    __shared__ int   toks[64];

    int tid = threadIdx.x;
    int m0 = blockIdx.y * 64;
    int n0 = blockIdx.x * 64;
    int g  = n0 >> 10;

    if (tid < 64) toks[tid] = x[m0 + tid];
    __syncthreads();

    int arow = tid & 63;
    int aseg = tid >> 6;
    const float* erow = emb + (size_t)toks[arow] * EE;

    int ty = tid >> 4, tx = tid & 15;
    int r0 = ty * 4, c0 = tx * 4;

    float acc[4][4];
#pragma unroll
    for (int i = 0; i < 4; i++)
#pragma unroll
        for (int j = 0; j < 4; j++) acc[i][j] = 0.f;

    for (int k0 = 0; k0 < 320; k0 += 32) {
#pragma unroll
        for (int i = 0; i < 8; i++) {
            int kk = aseg * 8 + i;
            int k  = k0 + kk;
            As[kk][arow] = (k < EE) ? erow[k] : 0.f;
        }
#pragma unroll
        for (int q = 0; q < 2; q++) {
            int f4 = tid * 2 + q;
            int kk = f4 >> 4;
            int c4 = (f4 & 15) * 4;
            int k  = k0 + kk;
            float4 v = make_float4(0.f, 0.f, 0.f, 0.f);
            if (k < EE) v = *(const float4*)(W + (size_t)k * G3 + n0 + c4);
            *(float4*)&Bs[kk][c4] = v;
        }
        __syncthreads();
#pragma unroll
        for (int kk = 0; kk < 32; kk++) {
            float4 a = *(const float4*)&As[kk][r0];
            float4 b = *(const float4*)&Bs[kk][c0];
            acc[0][0] += a.x * b.x; acc[0][1] += a.x * b.y; acc[0][2] += a.x * b.z; acc[0][3] += a.x * b.w;
            acc[1][0] += a.y * b.x; acc[1][1] += a.y * b.y; acc[1][2] += a.y * b.z; acc[1][3] += a.y * b.w;
            acc[2][0] += a.z * b.x; acc[2][1] += a.z * b.y; acc[2][2] += a.z * b.z; acc[2][3] += a.z * b.w;
            acc[3][0] += a.w * b.x; acc[3][1] += a.w * b.y; acc[3][2] += a.w * b.z; acc[3][3] += a.w * b.w;
        }
        __syncthreads();
    }

    float4 bv = *(const float4*)(bias0 + n0 + c0);
    int ubase = (n0 + c0) & 1023;
#pragma unroll
    for (int ii = 0; ii < 4; ii++) {
        int i  = m0 + r0 + ii;
        int bb = i >> 9;
        int tt = i & 511;
        float4 o;
        o.x = acc[ii][0] + bv.x;
        o.y = acc[ii][1] + bv.y;
        o.z = acc[ii][2] + bv.z;
        o.w = acc[ii][3] + bv.w;
        *(float4*)&g_xp[(((size_t)g * TT + tt) * BB + bb) * UU + ubase] = o;
    }
}

// ---------------------------------------------------------------------------
// Persistent WMMA GRU scan. 144 CTAs x 256 threads, 1 CTA/SM.
// A slice resident in smem; per step: stream B slice (4 chunks), 1024 wmma,
// store partials, prefetch xp, bar1, distributed epilogue (all CTAs), bar2.
// h_prev lives in registers (unit pinned to thread for all steps).
// ---------------------------------------------------------------------------
__device__ __forceinline__ void gbar_sync(unsigned target) {
    __syncthreads();
    if (threadIdx.x == 0) {
        __threadfence();
        atomicAdd(&g_bar, 1u);
        while (*(volatile unsigned*)&g_bar < target) { }
        __threadfence();
    }
    __syncthreads();
}

__global__ void __launch_bounds__(256, 1)
gru_wmma_kernel(const float* __restrict__ hidden0,
                const float* __restrict__ bias,
                float* __restrict__ out,
                int write_state) {
    extern __shared__ unsigned char sm[];
    __nv_bfloat16* Asm = (__nv_bfloat16*)sm;
    unsigned char* Bsm = sm + A_BYTES;

    int tid = threadIdx.x;
    int cta = blockIdx.x;
    int mt = cta / NSL;
    int s  = cta - mt * NSL;
    int w  = tid >> 5;
    int wm = w & 3;          // m-group (32 rows)
    int wn = w >> 2;         // n-group (32 cols)

    // Load resident A slice once.
    {
        const unsigned char* src = (const unsigned char*)g_Apack + (size_t)cta * A_BYTES;
        for (int i = tid; i < A_BYTES / 16; i += 256)
            cp16(sm + (size_t)i * 16, src + (size_t)i * 16);
        cpa_commit();
        asm volatile("cp.async.wait_group 0;\n");
    }
    __syncthreads();

    int kbase = s * KSL;     // column window in Bcat
    int brow = tid >> 2;     // 0..63 (B row per thread)
    int bq   = tid & 3;

    // Epilogue unit (static for all steps): unit = cta*UPC + tid, tid < UPC.
    int unit = cta * UPC + tid;
    bool edo = (tid < UPC) && (unit < NU);
    int eb = 0, eu4 = 0;
    float bzv[4] = {0,0,0,0}, brv[4] = {0,0,0,0}, bhv[4] = {0,0,0,0};
    float hpv[4] = {0,0,0,0};
    if (edo) {
        eb  = unit >> 8;
        eu4 = (unit & 255) << 2;
        float4 t4;
        t4 = *(const float4*)&bias[G3 + eu4];            bzv[0]=t4.x; bzv[1]=t4.y; bzv[2]=t4.z; bzv[3]=t4.w;
        t4 = *(const float4*)&bias[G3 + UU + eu4];       brv[0]=t4.x; brv[1]=t4.y; brv[2]=t4.z; brv[3]=t4.w;
        t4 = *(const float4*)&bias[G3 + 2 * UU + eu4];   bhv[0]=t4.x; bhv[1]=t4.y; bhv[2]=t4.z; bhv[3]=t4.w;
        t4 = *(const float4*)&hidden0[(size_t)eb * UU + eu4];
        hpv[0]=t4.x; hpv[1]=t4.y; hpv[2]=t4.z; hpv[3]=t4.w;
    }

    const __nv_bfloat16* Aw = Asm + (size_t)(wm * 32) * A_PITCH;
    float* gp = g_Pp + ((size_t)s * BB) * G3 + (size_t)(wn * 32) * G3 + mt * 128 + wm * 32;

    unsigned tgt = 0;
    for (int t = 0; t < TT; t++) {
        // Issue all 4 B-chunk copies from Bcat (ready from prep or prior epilogue).
#pragma unroll
        for (int kc = 0; kc < 4; kc++) {
            const unsigned char* srow = (const unsigned char*)
                (g_Bcat + (size_t)brow * G3 + kbase + kc * 128) + bq * 64;
            unsigned char* drow = Bsm + kc * BCH_BYTES + brow * (B_PITCH * 2) + bq * 64;
#pragma unroll
            for (int i = 0; i < 4; i++) cp16(drow + i * 16, srow + i * 16);
            cpa_commit();
        }

        wmma::fragment<wmma::accumulator, 16, 16, 16, float> acc[2][2];
#pragma unroll
        for (int i = 0; i < 2; i++)
#pragma unroll
            for (int j = 0; j < 2; j++) wmma::fill_fragment(acc[i][j], 0.0f);

#pragma unroll
        for (int kc = 0; kc < 4; kc++) {
            if      (kc == 0) asm volatile("cp.async.wait_group 3;\n");
            else if (kc == 1) asm volatile("cp.async.wait_group 2;\n");
            else if (kc == 2) asm volatile("cp.async.wait_group 1;\n");
            else              asm volatile("cp.async.wait_group 0;\n");
            __syncthreads();

            const __nv_bfloat16* Bb = (const __nv_bfloat16*)(Bsm + kc * BCH_BYTES);
#pragma unroll
            for (int kk = 0; kk < 8; kk++) {
                int kof = kc * 128 + kk * 16;
                wmma::fragment<wmma::matrix_a, 16, 16, 16, __nv_bfloat16, wmma::row_major> af[2];
                wmma::fragment<wmma::matrix_b, 16, 16, 16, __nv_bfloat16, wmma::col_major> bf[2];
                wmma::load_matrix_sync(af[0], Aw + kof, A_PITCH);
                wmma::load_matrix_sync(af[1], Aw + (size_t)16 * A_PITCH + kof, A_PITCH);
                wmma::load_matrix_sync(bf[0], Bb + (size_t)(wn * 32) * B_PITCH + kk * 16, B_PITCH);
                wmma::load_matrix_sync(bf[1], Bb + (size_t)(wn * 32 + 16) * B_PITCH + kk * 16, B_PITCH);
                wmma::mma_sync(acc[0][0], af[0], bf[0], acc[0][0]);
                wmma::mma_sync(acc[0][1], af[0], bf[1], acc[0][1]);
                wmma::mma_sync(acc[1][0], af[1], bf[0], acc[1][0]);
                wmma::mma_sync(acc[1][1], af[1], bf[1], acc[1][1]);
            }
        }

        // Store partials to g_Pp[s][b][m] (col_major: (m,n)->ptr[m + n*ldm]).
#pragma unroll
        for (int i = 0; i < 2; i++)
#pragma unroll
            for (int j = 0; j < 2; j++)
                wmma::store_matrix_sync(gp + (size_t)j * 16 * G3 + i * 16,
                                        acc[i][j], G3, wmma::mem_col_major);

        // Prefetch xp (independent of this step's GEMM) — hides under bar1.
        float xzv[4], xrv[4], xhv[4];
        if (edo) {
            float4 xz = *(const float4*)&g_xp[(((size_t)0 * TT + t) * BB + eb) * UU + eu4];
            float4 xr = *(const float4*)&g_xp[(((size_t)1 * TT + t) * BB + eb) * UU + eu4];
            float4 xh = *(const float4*)&g_xp[(((size_t)2 * TT + t) * BB + eb) * UU + eu4];
            xzv[0]=xz.x; xzv[1]=xz.y; xzv[2]=xz.z; xzv[3]=xz.w;
            xrv[0]=xr.x; xrv[1]=xr.y; xrv[2]=xr.z; xrv[3]=xr.w;
            xhv[0]=xh.x; xhv[1]=xh.y; xhv[2]=xh.z; xhv[3]=xh.w;
        }

        tgt += NCTA; gbar_sync(tgt);

        // Distributed epilogue: one float4-unit (b, u4..u4+3) per thread.
        if (edo) {
            float sz[4] = {0, 0, 0, 0}, sr[4] = {0, 0, 0, 0}, sh[4] = {0, 0, 0, 0};
#pragma unroll
            for (int si = 0; si < NSL; si++) {
                const float* pb = g_Pp + ((size_t)si * BB + eb) * G3;
                float4 vz = *(const float4*)(pb + eu4);
                float4 vr = *(const float4*)(pb + 1024 + eu4);
                float4 vh = *(const float4*)(pb + 2048 + eu4);
                sz[0] += vz.x; sz[1] += vz.y; sz[2] += vz.z; sz[3] += vz.w;
                sr[0] += vr.x; sr[1] += vr.y; sr[2] += vr.z; sr[3] += vr.w;
                sh[0] += vh.x; sh[1] += vh.y; sh[2] += vh.z; sh[3] += vh.w;
            }
            float hn[4], lo[4];
#pragma unroll
            for (int j = 0; j < 4; j++) {
                float z  = 1.f / (1.f + expf(-(xzv[j] + sz[j] + bzv[j])));
                float rg = 1.f / (1.f + expf(-(xrv[j] + sr[j] + brv[j])));
                float hh = tanhf(xhv[j] + rg * (sh[j] + bhv[j]));
                hn[j] = z * hpv[j] + (1.f - z) * hh;
                hpv[j] = hn[j];                       // h_prev stays in registers
                __nv_bfloat16 hi = __float2bfloat16(hn[j]);
                lo[j] = hn[j] - __bfloat162float(hi);
            }
            *(float4*)&out[((size_t)eb * TT + t) * UU + eu4] =
                make_float4(hn[0], hn[1], hn[2], hn[3]);
            uint2 hv = make_uint2(packbf2(hn[0], hn[1]), packbf2(hn[2], hn[3]));
            uint2 lv = make_uint2(packbf2(lo[0], lo[1]), packbf2(lo[2], lo[3]));
            *(uint2*)&g_Bcat[(size_t)eb * G3 + eu4] = hv;
            *(uint2*)&g_Bcat[(size_t)eb * G3 + 1024 + eu4] = lv;
            *(uint2*)&g_Bcat[(size_t)eb * G3 + 2048 + eu4] = hv;
            if (write_state && t == TT - 1)
                *(float4*)&out[(size_t)BB * TT * UU + (size_t)eb * UU + eu4] =
                    make_float4(hn[0], hn[1], hn[2], hn[3]);
        }

        tgt += NCTA; gbar_sync(tgt);
    }
}

// ---------------------------------------------------------------------------
extern "C" void kernel_launch(void* const* d_in, const int* in_sizes, int n_in,
                              void* d_out, int out_size) {
    const int*   x      = (const int*)d_in[0];
    const float* hidden = (const float*)d_in[1];
    const float* emb    = (const float*)d_in[2];
    const float* W      = (const float*)d_in[3];
    const float* Rk     = (const float*)d_in[4];
    const float* bias   = (const float*)d_in[5];
    float* out = (float*)d_out;

    int write_state = (out_size >= BB * TT * UU + BB * UU) ? 1 : 0;

    static int attr_done = 0;
    if (!attr_done) {
        cudaFuncSetAttribute(gru_wmma_kernel,
                             cudaFuncAttributeMaxDynamicSharedMemorySize, SMEM_BYTES);
        attr_done = 1;
    }

    init_bar_kernel<<<1, 1>>>();

    size_t ae = (size_t)G3 * G3;
    pack_A_kernel<<<(unsigned)((ae + 255) / 256), 256>>>(Rk);
    prep_B_kernel<<<(BB * UU + 255) / 256, 256>>>(hidden);

    dim3 gA(G3 / 64, (BB * TT) / 64);
    input_gemm_kernel<<<gA, 256>>>(x, emb, W, bias);

    gru_wmma_kernel<<<NCTA, 256, SMEM_BYTES>>>(hidden, bias, out, write_state);
}

// round 7
// speedup vs baseline: 2.2317x; 1.0276x over previous
#include <cuda_runtime.h>
#include <cuda_bf16.h>
#include <mma.h>
#include <cstdint>
#include <cstddef>

using namespace nvcuda;

#define BB 64
#define TT 512
#define EE 300
#define UU 1024
#define G3 3072
#define NCTA 144           // 24 m-tiles x 6 k-slices
#define NSL 6
#define KSL 512
#define A_PITCH 520        // 512 + 8 pad (conflict-free ldmatrix)
#define A_BYTES (128 * A_PITCH * 2)       // 133120
#define B_PITCH 136        // 128 + 8 pad
#define BCH_BYTES (64 * B_PITCH * 2)      // 17408
#define NBST 2                            // B ring stages
#define PS_LD 132                         // staging ldm (col-major, 128 rows + pad)
#define PS_BYTES (PS_LD * 64 * 4)         // 33792
#define SMEM_BYTES (A_BYTES + NBST * BCH_BYTES + PS_BYTES)   // 201728
#define NU2 (BB * (UU / 2))               // 32768 float2 epilogue units
#define UPC2 228                          // ceil(NU2 / NCTA)

// ---- static device scratch ----
__device__ float g_xp[(size_t)3 * TT * BB * UU];                     // [gate][t][b][u]
__device__ __align__(16) __nv_bfloat16 g_Apack[(size_t)NCTA * 128 * A_PITCH];
__device__ __align__(16) __nv_bfloat16 g_Bcat[(size_t)BB * G3];      // [b][hhi|hlo|hhi]
__device__ float g_Pp[(size_t)NSL * BB * G3];                        // [slice][b][m]
__device__ unsigned g_bar;

__global__ void init_bar_kernel() { g_bar = 0u; }

__device__ __forceinline__ void cp16(void* dst, const void* src) {
    unsigned d = (unsigned)__cvta_generic_to_shared(dst);
    asm volatile("cp.async.cg.shared.global [%0], [%1], 16;\n" :: "r"(d), "l"(src));
}
__device__ __forceinline__ void cpa_commit() {
    asm volatile("cp.async.commit_group;\n");
}
__device__ __forceinline__ unsigned packbf2(float a, float b) {
    __nv_bfloat16 ha = __float2bfloat16(a), hb = __float2bfloat16(b);
    unsigned short ua = *(unsigned short*)&ha, ub = *(unsigned short*)&hb;
    return (unsigned)ua | ((unsigned)ub << 16);
}

// ---------------------------------------------------------------------------
// Pack A' slices. cta = mt*6 + s; slice s covers k' = s*512.. of K'=3072:
//   k'<1024: Rhi*hhi   1024..2047: Rhi*hlo   2048..3071: Rlo*hhi
// ---------------------------------------------------------------------------
__global__ void pack_A_kernel(const float* __restrict__ Rk) {
    size_t idx = (size_t)blockIdx.x * 256 + threadIdx.x;
    if (idx >= (size_t)G3 * G3) return;
    int m  = (int)(idx / G3);
    int kp = (int)(idx - (size_t)m * G3);
    int s = kp >> 9;
    int j = kp & 511;
    int k = ((s & 1) << 9) + j;
    int region = s >> 1;
    float v = Rk[(size_t)k * G3 + m];
    __nv_bfloat16 hi = __float2bfloat16(v);
    __nv_bfloat16 wv = (region == 2) ? __float2bfloat16(v - __bfloat162float(hi)) : hi;
    int mt = m >> 7, ml = m & 127;
    g_Apack[(size_t)(mt * NSL + s) * (128 * A_PITCH) + ml * A_PITCH + j] = wv;
}

// ---------------------------------------------------------------------------
__global__ void prep_B_kernel(const float* __restrict__ hidden0) {
    int idx = blockIdx.x * 256 + threadIdx.x;
    if (idx >= BB * UU) return;
    int b = idx >> 10, u = idx & 1023;
    float v = hidden0[idx];
    __nv_bfloat16 hi = __float2bfloat16(v);
    __nv_bfloat16 lo = __float2bfloat16(v - __bfloat162float(hi));
    g_Bcat[(size_t)b * G3 + u] = hi;
    g_Bcat[(size_t)b * G3 + 1024 + u] = lo;
    g_Bcat[(size_t)b * G3 + 2048 + u] = hi;
}

// ---------------------------------------------------------------------------
// Input GEMM (fp32 SIMT): xp -> g_xp[gate][t][b][u]
// ---------------------------------------------------------------------------
__global__ void input_gemm_kernel(const int* __restrict__ x,
                                  const float* __restrict__ emb,
                                  const float* __restrict__ W,
                                  const float* __restrict__ bias0) {
    __shared__ float As[32][68];
    __shared__ float Bs[32][68];
    __shared__ int   toks[64];

    int tid = threadIdx.x;
    int m0 = blockIdx.y * 64;
    int n0 = blockIdx.x * 64;
    int g  = n0 >> 10;

    if (tid < 64) toks[tid] = x[m0 + tid];
    __syncthreads();

    int arow = tid & 63;
    int aseg = tid >> 6;
    const float* erow = emb + (size_t)toks[arow] * EE;

    int ty = tid >> 4, tx = tid & 15;
    int r0 = ty * 4, c0 = tx * 4;

    float acc[4][4];
#pragma unroll
    for (int i = 0; i < 4; i++)
#pragma unroll
        for (int j = 0; j < 4; j++) acc[i][j] = 0.f;

    for (int k0 = 0; k0 < 320; k0 += 32) {
#pragma unroll
        for (int i = 0; i < 8; i++) {
            int kk = aseg * 8 + i;
            int k  = k0 + kk;
            As[kk][arow] = (k < EE) ? erow[k] : 0.f;
        }
#pragma unroll
        for (int q = 0; q < 2; q++) {
            int f4 = tid * 2 + q;
            int kk = f4 >> 4;
            int c4 = (f4 & 15) * 4;
            int k  = k0 + kk;
            float4 v = make_float4(0.f, 0.f, 0.f, 0.f);
            if (k < EE) v = *(const float4*)(W + (size_t)k * G3 + n0 + c4);
            *(float4*)&Bs[kk][c4] = v;
        }
        __syncthreads();
#pragma unroll
        for (int kk = 0; kk < 32; kk++) {
            float4 a = *(const float4*)&As[kk][r0];
            float4 b = *(const float4*)&Bs[kk][c0];
            acc[0][0] += a.x * b.x; acc[0][1] += a.x * b.y; acc[0][2] += a.x * b.z; acc[0][3] += a.x * b.w;
            acc[1][0] += a.y * b.x; acc[1][1] += a.y * b.y; acc[1][2] += a.y * b.z; acc[1][3] += a.y * b.w;
            acc[2][0] += a.z * b.x; acc[2][1] += a.z * b.y; acc[2][2] += a.z * b.z; acc[2][3] += a.z * b.w;
            acc[3][0] += a.w * b.x; acc[3][1] += a.w * b.y; acc[3][2] += a.w * b.z; acc[3][3] += a.w * b.w;
        }
        __syncthreads();
    }

    float4 bv = *(const float4*)(bias0 + n0 + c0);
    int ubase = (n0 + c0) & 1023;
#pragma unroll
    for (int ii = 0; ii < 4; ii++) {
        int i  = m0 + r0 + ii;
        int bb = i >> 9;
        int tt = i & 511;
        float4 o;
        o.x = acc[ii][0] + bv.x;
        o.y = acc[ii][1] + bv.y;
        o.z = acc[ii][2] + bv.z;
        o.w = acc[ii][3] + bv.w;
        *(float4*)&g_xp[(((size_t)g * TT + tt) * BB + bb) * UU + ubase] = o;
    }
}

// ---------------------------------------------------------------------------
// Persistent WMMA GRU scan. 144 CTAs x 256 threads, 1 CTA/SM.
// A slice smem-resident; per step: 2-stage B ring, 1024 wmma, partials staged
// in smem then coalesced to g_Pp, bar1, distributed float2 epilogue, bar2.
// ---------------------------------------------------------------------------
__device__ __forceinline__ void gbar_sync(unsigned target) {
    __syncthreads();
    if (threadIdx.x == 0) {
        __threadfence();
        atomicAdd(&g_bar, 1u);
        while (*(volatile unsigned*)&g_bar < target) { }
        __threadfence();
    }
    __syncthreads();
}

__global__ void __launch_bounds__(256, 1)
gru_wmma_kernel(const float* __restrict__ hidden0,
                const float* __restrict__ bias,
                float* __restrict__ out,
                int write_state) {
    extern __shared__ unsigned char sm[];
    __nv_bfloat16* Asm = (__nv_bfloat16*)sm;
    unsigned char* Bsm = sm + A_BYTES;
    float* Ps = (float*)(sm + A_BYTES + NBST * BCH_BYTES);   // col-major [m + n*PS_LD]

    int tid = threadIdx.x;
    int cta = blockIdx.x;
    int mt = cta / NSL;
    int s  = cta - mt * NSL;
    int w  = tid >> 5;
    int wm = w & 3;          // m-group (32 rows)
    int wn = w >> 2;         // n-group (32 cols)

    // Load resident A slice once.
    {
        const unsigned char* src = (const unsigned char*)g_Apack + (size_t)cta * A_BYTES;
        for (int i = tid; i < A_BYTES / 16; i += 256)
            cp16(sm + (size_t)i * 16, src + (size_t)i * 16);
        cpa_commit();
        asm volatile("cp.async.wait_group 0;\n");
    }
    __syncthreads();

    int kbase = s * KSL;     // column window in Bcat
    int brow = tid >> 2;     // 0..63 (B row per thread)
    int bq   = tid & 3;

    // Epilogue unit (float2, static for all steps).
    int unit = cta * UPC2 + tid;
    bool edo = (tid < UPC2) && (unit < NU2);
    int eb = 0, eu2 = 0;
    float bzv[2] = {0,0}, brv[2] = {0,0}, bhv[2] = {0,0};
    float hpv[2] = {0,0};
    if (edo) {
        eb  = unit >> 9;
        eu2 = (unit & 511) << 1;
        float2 t2;
        t2 = *(const float2*)&bias[G3 + eu2];           bzv[0]=t2.x; bzv[1]=t2.y;
        t2 = *(const float2*)&bias[G3 + UU + eu2];      brv[0]=t2.x; brv[1]=t2.y;
        t2 = *(const float2*)&bias[G3 + 2 * UU + eu2];  bhv[0]=t2.x; bhv[1]=t2.y;
        t2 = *(const float2*)&hidden0[(size_t)eb * UU + eu2];
        hpv[0]=t2.x; hpv[1]=t2.y;
    }

    const __nv_bfloat16* Aw = Asm + (size_t)(wm * 32) * A_PITCH;
    float* gpp = g_Pp + ((size_t)s * BB) * G3 + mt * 128;   // + b*G3 + m

    unsigned tgt = 0;
    for (int t = 0; t < TT; t++) {
        // Prologue: issue first 2 B chunks.
#pragma unroll
        for (int kc = 0; kc < NBST; kc++) {
            const unsigned char* srow = (const unsigned char*)
                (g_Bcat + (size_t)brow * G3 + kbase + kc * 128) + bq * 64;
            unsigned char* drow = Bsm + kc * BCH_BYTES + brow * (B_PITCH * 2) + bq * 64;
#pragma unroll
            for (int i = 0; i < 4; i++) cp16(drow + i * 16, srow + i * 16);
            cpa_commit();
        }

        wmma::fragment<wmma::accumulator, 16, 16, 16, float> acc[2][2];
#pragma unroll
        for (int i = 0; i < 2; i++)
#pragma unroll
            for (int j = 0; j < 2; j++) wmma::fill_fragment(acc[i][j], 0.0f);

#pragma unroll
        for (int kc = 0; kc < 4; kc++) {
            if (kc < 3) asm volatile("cp.async.wait_group 1;\n");
            else        asm volatile("cp.async.wait_group 0;\n");
            __syncthreads();

            const __nv_bfloat16* Bb = (const __nv_bfloat16*)(Bsm + (kc & 1) * BCH_BYTES);
#pragma unroll
            for (int kk = 0; kk < 8; kk++) {
                int kof = kc * 128 + kk * 16;
                wmma::fragment<wmma::matrix_a, 16, 16, 16, __nv_bfloat16, wmma::row_major> af[2];
                wmma::fragment<wmma::matrix_b, 16, 16, 16, __nv_bfloat16, wmma::col_major> bf[2];
                wmma::load_matrix_sync(af[0], Aw + kof, A_PITCH);
                wmma::load_matrix_sync(af[1], Aw + (size_t)16 * A_PITCH + kof, A_PITCH);
                wmma::load_matrix_sync(bf[0], Bb + (size_t)(wn * 32) * B_PITCH + kk * 16, B_PITCH);
                wmma::load_matrix_sync(bf[1], Bb + (size_t)(wn * 32 + 16) * B_PITCH + kk * 16, B_PITCH);
                wmma::mma_sync(acc[0][0], af[0], bf[0], acc[0][0]);
                wmma::mma_sync(acc[0][1], af[0], bf[1], acc[0][1]);
                wmma::mma_sync(acc[1][0], af[1], bf[0], acc[1][0]);
                wmma::mma_sync(acc[1][1], af[1], bf[1], acc[1][1]);
            }
            __syncthreads();
            if (kc < 2) {
                int nc = kc + 2;
                const unsigned char* srow = (const unsigned char*)
                    (g_Bcat + (size_t)brow * G3 + kbase + nc * 128) + bq * 64;
                unsigned char* drow = Bsm + (nc & 1) * BCH_BYTES + brow * (B_PITCH * 2) + bq * 64;
#pragma unroll
                for (int i = 0; i < 4; i++) cp16(drow + i * 16, srow + i * 16);
                cpa_commit();
            }
        }

        // Stage partials in smem (col-major: (m,n) -> Ps[m + n*PS_LD]).
#pragma unroll
        for (int i = 0; i < 2; i++)
#pragma unroll
            for (int j = 0; j < 2; j++)
                wmma::store_matrix_sync(Ps + (wm * 32 + i * 16) + (size_t)(wn * 32 + j * 16) * PS_LD,
                                        acc[i][j], PS_LD, wmma::mem_col_major);

        // Prefetch xp — hides under staging copy + bar1.
        float xzv[2], xrv[2], xhv[2];
        if (edo) {
            float2 xz = *(const float2*)&g_xp[(((size_t)0 * TT + t) * BB + eb) * UU + eu2];
            float2 xr = *(const float2*)&g_xp[(((size_t)1 * TT + t) * BB + eb) * UU + eu2];
            float2 xh = *(const float2*)&g_xp[(((size_t)2 * TT + t) * BB + eb) * UU + eu2];
            xzv[0]=xz.x; xzv[1]=xz.y;
            xrv[0]=xr.x; xrv[1]=xr.y;
            xhv[0]=xh.x; xhv[1]=xh.y;
        }
        __syncthreads();

        // Coalesced copy staging -> g_Pp[s][b][mt*128 + m] (512B runs).
#pragma unroll
        for (int i = 0; i < 8; i++) {
            int lin = tid + i * 256;          // 0..2047
            int b = lin >> 5;
            int q = lin & 31;                 // float4 index within 128-float row
            float4 v = *(const float4*)&Ps[q * 4 + b * PS_LD];
            *(float4*)&gpp[(size_t)b * G3 + q * 4] = v;
        }

        tgt += NCTA; gbar_sync(tgt);

        // Distributed epilogue: one float2 unit (eb, eu2..eu2+1) per thread.
        if (edo) {
            float sz[2] = {0, 0}, sr[2] = {0, 0}, sh[2] = {0, 0};
#pragma unroll
            for (int si = 0; si < NSL; si++) {
                const float* pb = g_Pp + ((size_t)si * BB + eb) * G3;
                float2 vz = *(const float2*)(pb + eu2);
                float2 vr = *(const float2*)(pb + 1024 + eu2);
                float2 vh = *(const float2*)(pb + 2048 + eu2);
                sz[0] += vz.x; sz[1] += vz.y;
                sr[0] += vr.x; sr[1] += vr.y;
                sh[0] += vh.x; sh[1] += vh.y;
            }
            float hn[2], lo[2];
#pragma unroll
            for (int j = 0; j < 2; j++) {
                float z  = 1.f / (1.f + expf(-(xzv[j] + sz[j] + bzv[j])));
                float rg = 1.f / (1.f + expf(-(xrv[j] + sr[j] + brv[j])));
                float hh = tanhf(xhv[j] + rg * (sh[j] + bhv[j]));
                hn[j] = z * hpv[j] + (1.f - z) * hh;
                hpv[j] = hn[j];                       // h_prev stays in registers
                __nv_bfloat16 hi = __float2bfloat16(hn[j]);
                lo[j] = hn[j] - __bfloat162float(hi);
            }
            *(float2*)&out[((size_t)eb * TT + t) * UU + eu2] = make_float2(hn[0], hn[1]);
            unsigned hv = packbf2(hn[0], hn[1]);
            unsigned lv = packbf2(lo[0], lo[1]);
            *(unsigned*)&g_Bcat[(size_t)eb * G3 + eu2] = hv;
            *(unsigned*)&g_Bcat[(size_t)eb * G3 + 1024 + eu2] = lv;
            *(unsigned*)&g_Bcat[(size_t)eb * G3 + 2048 + eu2] = hv;
            if (write_state && t == TT - 1)
                *(float2*)&out[(size_t)BB * TT * UU + (size_t)eb * UU + eu2] =
                    make_float2(hn[0], hn[1]);
        }

        tgt += NCTA; gbar_sync(tgt);
    }
}

// ---------------------------------------------------------------------------
extern "C" void kernel_launch(void* const* d_in, const int* in_sizes, int n_in,
                              void* d_out, int out_size) {
    const int*   x      = (const int*)d_in[0];
    const float* hidden = (const float*)d_in[1];
    const float* emb    = (const float*)d_in[2];
    const float* W      = (const float*)d_in[3];
    const float* Rk     = (const float*)d_in[4];
    const float* bias   = (const float*)d_in[5];
    float* out = (float*)d_out;

    int write_state = (out_size >= BB * TT * UU + BB * UU) ? 1 : 0;

    static int attr_done = 0;
    if (!attr_done) {
        cudaFuncSetAttribute(gru_wmma_kernel,
                             cudaFuncAttributeMaxDynamicSharedMemorySize, SMEM_BYTES);
        attr_done = 1;
    }

    init_bar_kernel<<<1, 1>>>();

    size_t ae = (size_t)G3 * G3;
    pack_A_kernel<<<(unsigned)((ae + 255) / 256), 256>>>(Rk);
    prep_B_kernel<<<(BB * UU + 255) / 256, 256>>>(hidden);

    dim3 gA(G3 / 64, (BB * TT) / 64);
    input_gemm_kernel<<<gA, 256>>>(x, emb, W, bias);

    gru_wmma_kernel<<<NCTA, 256, SMEM_BYTES>>>(hidden, bias, out, write_state);
}